// round 10
// baseline (speedup 1.0000x reference)
#include <cuda_runtime.h>
#include <cstdint>

#define BDIM 8192
#define DDIM 1024
#define EDIM 32
#define ADIM 128
#define EG   4
#define NGRP (EDIM / EG)     // 8
#define BM   128
#define BN   128
#define BK   32              // 32 fp32 = 128 B per smem row
#define NKB  (DDIM / BK)     // 32
#define THREADS 512
#define TILE_BYTES (BM * BK * 4)             // 16384
#define STAGE      ((1 + EG) * TILE_BYTES)   // A + 4 B tiles = 81920
#define SMEM_DYN   (2 * STAGE)               // 163840 double buffered

// ---------------- device scratch ----------------
__device__ __align__(1024) float g_Xtf[(size_t)BDIM * DDIM];
__device__ __align__(1024) float g_Wtf[(size_t)EDIM * ADIM * DDIM];
__device__ float g_weights[BDIM * EDIM];
__device__ float g_scratch[(size_t)NGRP * BDIM * ADIM];

// ---------------- helpers ----------------
__device__ __forceinline__ uint32_t smem_u32(const void* p) {
    uint32_t a;
    asm("{ .reg .u64 t; cvta.to.shared.u64 t, %1; cvt.u32.u64 %0, t; }" : "=r"(a) : "l"(p));
    return a;
}
__device__ __forceinline__ void cp_async16(uint32_t dst, const void* src) {
    asm volatile("cp.async.cg.shared.global [%0], [%1], 16;" :: "r"(dst), "l"(src));
}
__device__ __forceinline__ void cp_commit() { asm volatile("cp.async.commit_group;"); }
__device__ __forceinline__ void cp_wait0()  { asm volatile("cp.async.wait_group 0;" ::: "memory"); }
__device__ __forceinline__ void cp_wait1()  { asm volatile("cp.async.wait_group 1;" ::: "memory"); }
__device__ __forceinline__ uint32_t sw128(uint32_t o) { return o ^ ((o >> 3) & 0x70); }
__device__ __forceinline__ uint32_t f2tf32(float v) {
    uint32_t t;
    asm("cvt.rna.tf32.f32 %0, %1;" : "=r"(t) : "f"(v));
    return t;
}
// scale a tf32-bit-pattern operand by s, re-round to tf32
__device__ __forceinline__ uint32_t scale_tf32(uint32_t a, float s) {
    return f2tf32(__uint_as_float(a) * s);
}
__device__ __forceinline__ void mma_tf32(float d[4], const uint32_t a[4], const uint32_t b[2]) {
    asm volatile(
        "mma.sync.aligned.m16n8k8.row.col.f32.tf32.tf32.f32 "
        "{%0,%1,%2,%3}, {%4,%5,%6,%7}, {%8,%9}, {%0,%1,%2,%3};"
        : "+f"(d[0]), "+f"(d[1]), "+f"(d[2]), "+f"(d[3])
        : "r"(a[0]), "r"(a[1]), "r"(a[2]), "r"(a[3]), "r"(b[0]), "r"(b[1]));
}

// ---------------------------------------------------------------------------
// Gating: logits + gumbel + softmax -> g_weights
// ---------------------------------------------------------------------------
__global__ __launch_bounds__(256) void gating_kernel(
    const float* __restrict__ x, const float* __restrict__ W_att,
    const float* __restrict__ b_att, const float* __restrict__ adaptive_bias,
    const float* __restrict__ gumbel_u)
{
    const int warp = threadIdx.x >> 5, lane = threadIdx.x & 31;
    const int b = blockIdx.x * 8 + warp;
    __shared__ float logits_s[8][EDIM];

    const float* xrow = x + (size_t)b * DDIM;
    float xr[32];
#pragma unroll
    for (int k = 0; k < 32; k++) xr[k] = xrow[k * 32 + lane];

    for (int e = 0; e < EDIM; e++) {
        const float* wrow = W_att + (size_t)e * DDIM;
        float p = 0.f;
#pragma unroll
        for (int k = 0; k < 32; k++) p = fmaf(xr[k], wrow[k * 32 + lane], p);
#pragma unroll
        for (int o = 16; o; o >>= 1) p += __shfl_xor_sync(0xffffffffu, p, o);
        if (lane == 0) logits_s[warp][e] = p;
    }
    __syncwarp();

    float l = logits_s[warp][lane] + b_att[lane] + adaptive_bias[lane];
    float u = gumbel_u[(size_t)b * EDIM + lane];
    float g = -logf(-logf(u + 1e-10f) + 1e-10f);
    float z = l + g;
    float m = z;
#pragma unroll
    for (int o = 16; o; o >>= 1) m = fmaxf(m, __shfl_xor_sync(0xffffffffu, m, o));
    float p = expf(z - m);
    float s = p;
#pragma unroll
    for (int o = 16; o; o >>= 1) s += __shfl_xor_sync(0xffffffffu, s, o);
    g_weights[(size_t)b * EDIM + lane] = p / s;
}

// ---------------------------------------------------------------------------
// Pre-round x and W_strat to tf32 precision (stored as f32 bits)
// ---------------------------------------------------------------------------
__global__ __launch_bounds__(256) void convert_x_tf(const float* __restrict__ x) {
    const size_t i4 = (size_t)blockIdx.x * 256 + threadIdx.x;
    float4 v = ((const float4*)x)[i4];
    uint4 o;
    o.x = f2tf32(v.x); o.y = f2tf32(v.y); o.z = f2tf32(v.z); o.w = f2tf32(v.w);
    ((uint4*)g_Xtf)[i4] = o;
}
__global__ __launch_bounds__(256) void convert_w_tf(const float* __restrict__ W_strat) {
    const size_t i4 = (size_t)blockIdx.x * 256 + threadIdx.x;
    float4 v = ((const float4*)W_strat)[i4];
    uint4 o;
    o.x = f2tf32(v.x); o.y = f2tf32(v.y); o.z = f2tf32(v.z); o.w = f2tf32(v.w);
    ((uint4*)g_Wtf)[i4] = o;
}

// ---------------------------------------------------------------------------
// TF32 mma.sync GEMM with gating weight folded into the A operand:
//   sum_e w_e * (x . W_e) == sum_e (w_e * x) . W_e
// All HMMAs (4 experts x 4 ks per kb) accumulate into ONE accumulator set;
// tensor results are never read until the epilogue -> no mid-loop RAW stalls.
// ---------------------------------------------------------------------------
__global__ __launch_bounds__(THREADS, 1) void gemm_tf32(const float* __restrict__ b_strat) {
    extern __shared__ char sm[];
    __shared__ float bs_s[EG][BN];
    __shared__ float w_s[EG][BM];

    const int tid = threadIdx.x, wid = tid >> 5, lane = tid & 31;
    const int wm = wid & 3, wn = wid >> 2;          // warp grid 4m x 4n
    const int eg = blockIdx.x & (NGRP - 1);
    const int mt = blockIdx.x >> 3;
    const int row0 = mt * BM;

    {   // stage bias + gating weights (512 elements each)
        (&bs_s[0][0])[tid] = b_strat[(size_t)(eg * EG) * ADIM + tid];
        const int e = tid >> 7, r = tid & 127;
        w_s[e][r] = g_weights[(size_t)(row0 + r) * EDIM + eg * EG + e];
    }

    const uint32_t sbase = smem_u32(sm);

    auto load_stage = [&](int b, int kb) {
        const uint32_t ab = sbase + b * STAGE;
        const char* xs = (const char*)g_Xtf + ((size_t)row0 * DDIM + kb * BK) * 4;
#pragma unroll
        for (int i = 0; i < 2; i++) {
            const int q = tid + THREADS * i, r = q >> 3, ch = (q & 7) * 16;
            cp_async16(ab + sw128(r * 128 + ch), xs + (size_t)r * DDIM * 4 + ch);
        }
#pragma unroll
        for (int e = 0; e < EG; e++) {
            const uint32_t bb = ab + (1 + e) * TILE_BYTES;
            const char* ws = (const char*)g_Wtf +
                             ((size_t)(eg * EG + e) * ADIM * DDIM + kb * BK) * 4;
#pragma unroll
            for (int i = 0; i < 2; i++) {
                const int q = tid + THREADS * i, r = q >> 3, ch = (q & 7) * 16;
                cp_async16(bb + sw128(r * 128 + ch), ws + (size_t)r * DDIM * 4 + ch);
            }
        }
        cp_commit();
    };

    // per-thread gating weights for own fragment rows:
    // f in {0,1}: rows wm*32 + f*16 + (lane>>2) and +8
    float wA[EG][2][2];
    __syncthreads();
#pragma unroll
    for (int e = 0; e < EG; e++)
#pragma unroll
        for (int f = 0; f < 2; f++) {
            const int r1 = wm * 32 + f * 16 + (lane >> 2);
            wA[e][f][0] = w_s[e][r1];
            wA[e][f][1] = w_s[e][r1 + 8];
        }

    float accf[2][4][4];
#pragma unroll
    for (int f = 0; f < 2; f++)
#pragma unroll
        for (int j = 0; j < 4; j++)
#pragma unroll
            for (int d = 0; d < 4; d++) accf[f][j][d] = 0.f;

    load_stage(0, 0);

    for (int kb = 0; kb < NKB; kb++) {
        const int buf = kb & 1;
        const bool more = (kb + 1 < NKB);
        if (more) load_stage(buf ^ 1, kb + 1);
        if (more) cp_wait1(); else cp_wait0();
        __syncthreads();

        const uint32_t ab = sbase + buf * STAGE;

        // A fragments for all 4 ks, loaded once per kb
        uint32_t afr[4][2][4];
#pragma unroll
        for (int ks = 0; ks < 4; ks++)
#pragma unroll
            for (int f = 0; f < 2; f++) {
                const int m0 = wm * 32 + f * 16;
                const uint32_t row = m0 + (lane & 15);
                const uint32_t byt = ks * 32 + (lane >> 4) * 16;
                const uint32_t addr = ab + sw128(row * 128 + byt);
                asm volatile(
                    "ldmatrix.sync.aligned.m8n8.x4.shared.b16 {%0,%1,%2,%3}, [%4];"
                    : "=r"(afr[ks][f][0]), "=r"(afr[ks][f][1]),
                      "=r"(afr[ks][f][2]), "=r"(afr[ks][f][3])
                    : "r"(addr));
            }

#pragma unroll
        for (int e = 0; e < EG; e++) {
            const uint32_t bb = ab + (1 + e) * TILE_BYTES;
#pragma unroll
            for (int ks = 0; ks < 4; ks++) {
                uint32_t bfr[2][4];
#pragma unroll
                for (int jp = 0; jp < 2; jp++) {
                    const int n0 = wn * 32 + jp * 16;
                    const uint32_t row = n0 + ((lane >> 4) & 1) * 8 + (lane & 7);
                    const uint32_t byt = ks * 32 + ((lane >> 3) & 1) * 16;
                    const uint32_t addr = bb + sw128(row * 128 + byt);
                    asm volatile(
                        "ldmatrix.sync.aligned.m8n8.x4.shared.b16 {%0,%1,%2,%3}, [%4];"
                        : "=r"(bfr[jp][0]), "=r"(bfr[jp][1]), "=r"(bfr[jp][2]), "=r"(bfr[jp][3])
                        : "r"(addr));
                }
                // scale A fragment rows by gating weight, re-round to tf32
#pragma unroll
                for (int f = 0; f < 2; f++) {
                    uint32_t sa[4];
                    sa[0] = scale_tf32(afr[ks][f][0], wA[e][f][0]);
                    sa[1] = scale_tf32(afr[ks][f][1], wA[e][f][1]);
                    sa[2] = scale_tf32(afr[ks][f][2], wA[e][f][0]);
                    sa[3] = scale_tf32(afr[ks][f][3], wA[e][f][1]);
#pragma unroll
                    for (int jp = 0; jp < 2; jp++) {
                        mma_tf32(accf[f][2 * jp + 0], sa, &bfr[jp][0]);
                        mma_tf32(accf[f][2 * jp + 1], sa, &bfr[jp][2]);
                    }
                }
            }
        }
        __syncthreads();
    }

    // add bias term: accf += sum_e w[row,e] * bias[e,col]
#pragma unroll
    for (int e = 0; e < EG; e++) {
#pragma unroll
        for (int f = 0; f < 2; f++) {
            const float w1 = wA[e][f][0], w2 = wA[e][f][1];
#pragma unroll
            for (int j = 0; j < 4; j++) {
                const int c0 = wn * 32 + j * 8 + (lane & 3) * 2;
                const float b0 = bs_s[e][c0], b1 = bs_s[e][c0 + 1];
                accf[f][j][0] = fmaf(w1, b0, accf[f][j][0]);
                accf[f][j][1] = fmaf(w1, b1, accf[f][j][1]);
                accf[f][j][2] = fmaf(w2, b0, accf[f][j][2]);
                accf[f][j][3] = fmaf(w2, b1, accf[f][j][3]);
            }
        }
    }

    // write to per-group scratch
#pragma unroll
    for (int f = 0; f < 2; f++) {
        const int r1 = row0 + wm * 32 + f * 16 + (lane >> 2);
#pragma unroll
        for (int j = 0; j < 4; j++) {
            const int c0 = wn * 32 + j * 8 + (lane & 3) * 2;
            float* base = g_scratch + (size_t)eg * BDIM * ADIM;
            *(float2*)&base[(size_t)r1 * ADIM + c0] =
                make_float2(accf[f][j][0], accf[f][j][1]);
            *(float2*)&base[(size_t)(r1 + 8) * ADIM + c0] =
                make_float2(accf[f][j][2], accf[f][j][3]);
        }
    }
}

// ---------------------------------------------------------------------------
// Final reduce: out = sum over 8 expert-group partials
// ---------------------------------------------------------------------------
__global__ __launch_bounds__(256) void reduce_kernel(float* __restrict__ out) {
    const size_t idx = (size_t)blockIdx.x * 256 + threadIdx.x;
    const float4* s = (const float4*)g_scratch;
    float4 a = s[idx];
#pragma unroll
    for (int g = 1; g < NGRP; g++) {
        float4 t = s[(size_t)g * (BDIM * ADIM / 4) + idx];
        a.x += t.x; a.y += t.y; a.z += t.z; a.w += t.w;
    }
    ((float4*)out)[idx] = a;
}

// ---------------------------------------------------------------------------
extern "C" void kernel_launch(void* const* d_in, const int* in_sizes, int n_in,
                              void* d_out, int out_size) {
    const float* x             = (const float*)d_in[0];
    const float* W_att         = (const float*)d_in[1];
    const float* b_att         = (const float*)d_in[2];
    const float* adaptive_bias = (const float*)d_in[3];
    const float* W_strat       = (const float*)d_in[4];
    const float* b_strat       = (const float*)d_in[5];
    const float* gumbel_u      = (const float*)d_in[6];
    float* out = (float*)d_out;

    cudaFuncSetAttribute(gemm_tf32, cudaFuncAttributeMaxDynamicSharedMemorySize, SMEM_DYN);

    gating_kernel<<<BDIM / 8, 256>>>(x, W_att, b_att, adaptive_bias, gumbel_u);
    convert_x_tf<<<(BDIM * DDIM / 4) / 256, 256>>>(x);
    convert_w_tf<<<(EDIM * ADIM * DDIM / 4) / 256, 256>>>(W_strat);
    gemm_tf32<<<(BDIM / BM) * NGRP, THREADS, SMEM_DYN>>>(b_strat);
    reduce_kernel<<<(BDIM * ADIM / 4) / 256, 256>>>(out);
}

// round 11
// speedup vs baseline: 1.1327x; 1.1327x over previous
#include <cuda_runtime.h>
#include <cstdint>

#define BDIM 8192
#define DDIM 1024
#define EDIM 32
#define ADIM 128
#define EG   4
#define NGRP (EDIM / EG)     // 8
#define BM   128
#define BN   128
#define BK   32              // 32 fp32 = 128 B per smem row
#define NKB  (DDIM / BK)     // 32
#define THREADS 512
#define TILE_BYTES (BM * BK * 4)             // 16384
#define STAGE      ((1 + EG) * TILE_BYTES)   // A + 4 B tiles = 81920
#define SMEM_DYN   (2 * STAGE)               // 163840 double buffered

// ---------------- device scratch ----------------
__device__ __align__(1024) float g_Xtf[(size_t)BDIM * DDIM];
__device__ __align__(1024) float g_Wtf[(size_t)EDIM * ADIM * DDIM];
__device__ float g_weights[BDIM * EDIM];
__device__ float g_scratch[(size_t)NGRP * BDIM * ADIM];

// ---------------- helpers ----------------
__device__ __forceinline__ uint32_t smem_u32(const void* p) {
    uint32_t a;
    asm("{ .reg .u64 t; cvta.to.shared.u64 t, %1; cvt.u32.u64 %0, t; }" : "=r"(a) : "l"(p));
    return a;
}
__device__ __forceinline__ void cp_async16(uint32_t dst, const void* src) {
    asm volatile("cp.async.cg.shared.global [%0], [%1], 16;" :: "r"(dst), "l"(src));
}
__device__ __forceinline__ void cp_commit() { asm volatile("cp.async.commit_group;"); }
__device__ __forceinline__ void cp_wait0()  { asm volatile("cp.async.wait_group 0;" ::: "memory"); }
__device__ __forceinline__ uint32_t sw128(uint32_t o) { return o ^ ((o >> 3) & 0x70); }
__device__ __forceinline__ uint32_t f2tf32(float v) {
    uint32_t t;
    asm("cvt.rna.tf32.f32 %0, %1;" : "=r"(t) : "f"(v));
    return t;
}
// scale a tf32 operand by s WITHOUT re-rounding: HMMA's tf32 datapath reads
// the high bits; the extra low mantissa bits are truncated by HW (<=2^-11 rel).
__device__ __forceinline__ uint32_t scale_tf32_fast(uint32_t a, float s) {
    return __float_as_uint(__uint_as_float(a) * s);
}
__device__ __forceinline__ void mma_tf32(float d[4], const uint32_t a[4], const uint32_t b[2]) {
    asm volatile(
        "mma.sync.aligned.m16n8k8.row.col.f32.tf32.tf32.f32 "
        "{%0,%1,%2,%3}, {%4,%5,%6,%7}, {%8,%9}, {%0,%1,%2,%3};"
        : "+f"(d[0]), "+f"(d[1]), "+f"(d[2]), "+f"(d[3])
        : "r"(a[0]), "r"(a[1]), "r"(a[2]), "r"(a[3]), "r"(b[0]), "r"(b[1]));
}

// ---------------------------------------------------------------------------
// Gating: logits + gumbel + softmax -> g_weights
// ---------------------------------------------------------------------------
__global__ __launch_bounds__(256) void gating_kernel(
    const float* __restrict__ x, const float* __restrict__ W_att,
    const float* __restrict__ b_att, const float* __restrict__ adaptive_bias,
    const float* __restrict__ gumbel_u)
{
    const int warp = threadIdx.x >> 5, lane = threadIdx.x & 31;
    const int b = blockIdx.x * 8 + warp;
    __shared__ float logits_s[8][EDIM];

    const float* xrow = x + (size_t)b * DDIM;
    float xr[32];
#pragma unroll
    for (int k = 0; k < 32; k++) xr[k] = xrow[k * 32 + lane];

    for (int e = 0; e < EDIM; e++) {
        const float* wrow = W_att + (size_t)e * DDIM;
        float p = 0.f;
#pragma unroll
        for (int k = 0; k < 32; k++) p = fmaf(xr[k], wrow[k * 32 + lane], p);
#pragma unroll
        for (int o = 16; o; o >>= 1) p += __shfl_xor_sync(0xffffffffu, p, o);
        if (lane == 0) logits_s[warp][e] = p;
    }
    __syncwarp();

    float l = logits_s[warp][lane] + b_att[lane] + adaptive_bias[lane];
    float u = gumbel_u[(size_t)b * EDIM + lane];
    float g = -logf(-logf(u + 1e-10f) + 1e-10f);
    float z = l + g;
    float m = z;
#pragma unroll
    for (int o = 16; o; o >>= 1) m = fmaxf(m, __shfl_xor_sync(0xffffffffu, m, o));
    float p = expf(z - m);
    float s = p;
#pragma unroll
    for (int o = 16; o; o >>= 1) s += __shfl_xor_sync(0xffffffffu, s, o);
    g_weights[(size_t)b * EDIM + lane] = p / s;
}

// ---------------------------------------------------------------------------
// Pre-round x and W_strat to tf32 precision (stored as f32 bits)
// ---------------------------------------------------------------------------
__global__ __launch_bounds__(256) void convert_x_tf(const float* __restrict__ x) {
    const size_t i4 = (size_t)blockIdx.x * 256 + threadIdx.x;
    float4 v = ((const float4*)x)[i4];
    uint4 o;
    o.x = f2tf32(v.x); o.y = f2tf32(v.y); o.z = f2tf32(v.z); o.w = f2tf32(v.w);
    ((uint4*)g_Xtf)[i4] = o;
}
__global__ __launch_bounds__(256) void convert_w_tf(const float* __restrict__ W_strat) {
    const size_t i4 = (size_t)blockIdx.x * 256 + threadIdx.x;
    float4 v = ((const float4*)W_strat)[i4];
    uint4 o;
    o.x = f2tf32(v.x); o.y = f2tf32(v.y); o.z = f2tf32(v.z); o.w = f2tf32(v.w);
    ((uint4*)g_Wtf)[i4] = o;
}

// ---------------------------------------------------------------------------
// TF32 mma.sync GEMM, gating weight folded into the A operand.
// Optimized: hoisted swizzle algebra (sw128(row*128+byt) = row*128 +
// (byt ^ ((row&7)<<4)) for byt<128), FMUL-only A scaling, one sync per kb.
// ---------------------------------------------------------------------------
__global__ __launch_bounds__(THREADS, 1) void gemm_tf32(const float* __restrict__ b_strat) {
    extern __shared__ char sm[];
    __shared__ float bs_s[EG][BN];
    __shared__ float w_s[EG][BM];

    const int tid = threadIdx.x, wid = tid >> 5, lane = tid & 31;
    const int wm = wid & 3, wn = wid >> 2;          // warp grid 4m x 4n
    const int eg = blockIdx.x & (NGRP - 1);
    const int mt = blockIdx.x >> 3;
    const int row0 = mt * BM;

    {   // stage bias + gating weights (512 elements each)
        (&bs_s[0][0])[tid] = b_strat[(size_t)(eg * EG) * ADIM + tid];
        const int e = tid >> 7, r = tid & 127;
        w_s[e][r] = g_weights[(size_t)(row0 + r) * EDIM + eg * EG + e];
    }

    const uint32_t sbase = smem_u32(sm);

    auto load_stage = [&](int b, int kb) {
        const uint32_t ab = sbase + b * STAGE;
        const char* xs = (const char*)g_Xtf + ((size_t)row0 * DDIM + kb * BK) * 4;
#pragma unroll
        for (int i = 0; i < 2; i++) {
            const int q = tid + THREADS * i, r = q >> 3, ch = (q & 7) * 16;
            cp_async16(ab + sw128(r * 128 + ch), xs + (size_t)r * DDIM * 4 + ch);
        }
#pragma unroll
        for (int e = 0; e < EG; e++) {
            const uint32_t bb = ab + (1 + e) * TILE_BYTES;
            const char* ws = (const char*)g_Wtf +
                             ((size_t)(eg * EG + e) * ADIM * DDIM + kb * BK) * 4;
#pragma unroll
            for (int i = 0; i < 2; i++) {
                const int q = tid + THREADS * i, r = q >> 3, ch = (q & 7) * 16;
                cp_async16(bb + sw128(r * 128 + ch), ws + (size_t)r * DDIM * 4 + ch);
            }
        }
        cp_commit();
    };

    // hoisted per-thread fragment addressing:
    // A rows (f=0,1): row = wm*32 + f*16 + (lane&15)
    uint32_t aBase[2], aXor[2];
#pragma unroll
    for (int f = 0; f < 2; f++) {
        const uint32_t row = wm * 32 + f * 16 + (lane & 15);
        aBase[f] = row * 128 + 0;       // byt added per-ks below
        aXor[f]  = (row & 7) << 4;
    }
    const uint32_t aByt = (lane >> 4) * 16;   // 0 or 16
    // B rows (jp=0,1): row = wn*32 + jp*16 + ((lane>>4)&1)*8 + (lane&7)
    uint32_t bBase[2], bXor[2];
#pragma unroll
    for (int jp = 0; jp < 2; jp++) {
        const uint32_t row = wn * 32 + jp * 16 + ((lane >> 4) & 1) * 8 + (lane & 7);
        bBase[jp] = row * 128;
        bXor[jp]  = (row & 7) << 4;
    }
    const uint32_t bByt = ((lane >> 3) & 1) * 16;  // 0 or 16

    // per-thread gating weights for own fragment rows
    float wA[EG][2][2];
    __syncthreads();
#pragma unroll
    for (int e = 0; e < EG; e++)
#pragma unroll
        for (int f = 0; f < 2; f++) {
            const int r1 = wm * 32 + f * 16 + (lane >> 2);
            wA[e][f][0] = w_s[e][r1];
            wA[e][f][1] = w_s[e][r1 + 8];
        }

    float accf[2][4][4];
#pragma unroll
    for (int f = 0; f < 2; f++)
#pragma unroll
        for (int j = 0; j < 4; j++)
#pragma unroll
            for (int d = 0; d < 4; d++) accf[f][j][d] = 0.f;

    load_stage(0, 0);

    for (int kb = 0; kb < NKB; kb++) {
        const int buf = kb & 1;
        cp_wait0();               // only this kb's group is in flight
        __syncthreads();          // data ready; all LDSMs of kb-1 done

        if (kb + 1 < NKB) load_stage(buf ^ 1, kb + 1);   // overlaps compute

        const uint32_t ab = sbase + buf * STAGE;

        // A fragments for all 4 ks
        uint32_t afr[4][2][4];
#pragma unroll
        for (int ks = 0; ks < 4; ks++)
#pragma unroll
            for (int f = 0; f < 2; f++) {
                const uint32_t addr = ab + aBase[f] + ((ks * 32 + aByt) ^ aXor[f]);
                asm volatile(
                    "ldmatrix.sync.aligned.m8n8.x4.shared.b16 {%0,%1,%2,%3}, [%4];"
                    : "=r"(afr[ks][f][0]), "=r"(afr[ks][f][1]),
                      "=r"(afr[ks][f][2]), "=r"(afr[ks][f][3])
                    : "r"(addr));
            }

#pragma unroll
        for (int e = 0; e < EG; e++) {
            const uint32_t bb = ab + (1 + e) * TILE_BYTES;
#pragma unroll
            for (int ks = 0; ks < 4; ks++) {
                uint32_t bfr[2][4];
#pragma unroll
                for (int jp = 0; jp < 2; jp++) {
                    const uint32_t addr = bb + bBase[jp] + ((ks * 32 + bByt) ^ bXor[jp]);
                    asm volatile(
                        "ldmatrix.sync.aligned.m8n8.x4.shared.b16 {%0,%1,%2,%3}, [%4];"
                        : "=r"(bfr[jp][0]), "=r"(bfr[jp][1]), "=r"(bfr[jp][2]), "=r"(bfr[jp][3])
                        : "r"(addr));
                }
#pragma unroll
                for (int f = 0; f < 2; f++) {
                    uint32_t sa[4];
                    sa[0] = scale_tf32_fast(afr[ks][f][0], wA[e][f][0]);
                    sa[1] = scale_tf32_fast(afr[ks][f][1], wA[e][f][1]);
                    sa[2] = scale_tf32_fast(afr[ks][f][2], wA[e][f][0]);
                    sa[3] = scale_tf32_fast(afr[ks][f][3], wA[e][f][1]);
#pragma unroll
                    for (int jp = 0; jp < 2; jp++) {
                        mma_tf32(accf[f][2 * jp + 0], sa, &bfr[jp][0]);
                        mma_tf32(accf[f][2 * jp + 1], sa, &bfr[jp][2]);
                    }
                }
            }
        }
    }

    // add bias term: accf += sum_e w[row,e] * bias[e,col]
#pragma unroll
    for (int e = 0; e < EG; e++) {
#pragma unroll
        for (int f = 0; f < 2; f++) {
            const float w1 = wA[e][f][0], w2 = wA[e][f][1];
#pragma unroll
            for (int j = 0; j < 4; j++) {
                const int c0 = wn * 32 + j * 8 + (lane & 3) * 2;
                const float b0 = bs_s[e][c0], b1 = bs_s[e][c0 + 1];
                accf[f][j][0] = fmaf(w1, b0, accf[f][j][0]);
                accf[f][j][1] = fmaf(w1, b1, accf[f][j][1]);
                accf[f][j][2] = fmaf(w2, b0, accf[f][j][2]);
                accf[f][j][3] = fmaf(w2, b1, accf[f][j][3]);
            }
        }
    }

    // write to per-group scratch
#pragma unroll
    for (int f = 0; f < 2; f++) {
        const int r1 = row0 + wm * 32 + f * 16 + (lane >> 2);
#pragma unroll
        for (int j = 0; j < 4; j++) {
            const int c0 = wn * 32 + j * 8 + (lane & 3) * 2;
            float* base = g_scratch + (size_t)eg * BDIM * ADIM;
            *(float2*)&base[(size_t)r1 * ADIM + c0] =
                make_float2(accf[f][j][0], accf[f][j][1]);
            *(float2*)&base[(size_t)(r1 + 8) * ADIM + c0] =
                make_float2(accf[f][j][2], accf[f][j][3]);
        }
    }
}

// ---------------------------------------------------------------------------
// Final reduce: out = sum over 8 expert-group partials
// ---------------------------------------------------------------------------
__global__ __launch_bounds__(256) void reduce_kernel(float* __restrict__ out) {
    const size_t idx = (size_t)blockIdx.x * 256 + threadIdx.x;
    const float4* s = (const float4*)g_scratch;
    float4 a = s[idx];
#pragma unroll
    for (int g = 1; g < NGRP; g++) {
        float4 t = s[(size_t)g * (BDIM * ADIM / 4) + idx];
        a.x += t.x; a.y += t.y; a.z += t.z; a.w += t.w;
    }
    ((float4*)out)[idx] = a;
}

// ---------------------------------------------------------------------------
extern "C" void kernel_launch(void* const* d_in, const int* in_sizes, int n_in,
                              void* d_out, int out_size) {
    const float* x             = (const float*)d_in[0];
    const float* W_att         = (const float*)d_in[1];
    const float* b_att         = (const float*)d_in[2];
    const float* adaptive_bias = (const float*)d_in[3];
    const float* W_strat       = (const float*)d_in[4];
    const float* b_strat       = (const float*)d_in[5];
    const float* gumbel_u      = (const float*)d_in[6];
    float* out = (float*)d_out;

    cudaFuncSetAttribute(gemm_tf32, cudaFuncAttributeMaxDynamicSharedMemorySize, SMEM_DYN);

    gating_kernel<<<BDIM / 8, 256>>>(x, W_att, b_att, adaptive_bias, gumbel_u);
    convert_x_tf<<<(BDIM * DDIM / 4) / 256, 256>>>(x);
    convert_w_tf<<<(EDIM * ADIM * DDIM / 4) / 256, 256>>>(W_strat);
    gemm_tf32<<<(BDIM / BM) * NGRP, THREADS, SMEM_DYN>>>(b_strat);
    reduce_kernel<<<(BDIM * ADIM / 4) / 256, 256>>>(out);
}

// round 12
// speedup vs baseline: 1.1506x; 1.0158x over previous
#include <cuda_runtime.h>
#include <cstdint>

#define BDIM 8192
#define DDIM 1024
#define EDIM 32
#define ADIM 128
#define EG   4
#define NGRP (EDIM / EG)     // 8
#define BM   128
#define BN   128
#define BK   32              // 32 fp32 = 128 B per smem row
#define NKB  (DDIM / BK)     // 32
#define THREADS 512
#define TILE_BYTES (BM * BK * 4)             // 16384
#define STAGE      ((1 + EG) * TILE_BYTES)   // A + 4 B tiles = 81920
#define SMEM_DYN   (2 * STAGE)               // 163840 double buffered

// ---------------- device scratch ----------------
__device__ __align__(1024) float g_Wtf[(size_t)EDIM * ADIM * DDIM];
__device__ float g_weights[BDIM * EDIM];
__device__ float g_scratch[(size_t)NGRP * BDIM * ADIM];

// ---------------- helpers ----------------
__device__ __forceinline__ uint32_t smem_u32(const void* p) {
    uint32_t a;
    asm("{ .reg .u64 t; cvta.to.shared.u64 t, %1; cvt.u32.u64 %0, t; }" : "=r"(a) : "l"(p));
    return a;
}
__device__ __forceinline__ void cp_async16(uint32_t dst, const void* src) {
    asm volatile("cp.async.cg.shared.global [%0], [%1], 16;" :: "r"(dst), "l"(src));
}
__device__ __forceinline__ void cp_commit() { asm volatile("cp.async.commit_group;"); }
__device__ __forceinline__ void cp_wait0()  { asm volatile("cp.async.wait_group 0;" ::: "memory"); }
__device__ __forceinline__ uint32_t sw128(uint32_t o) { return o ^ ((o >> 3) & 0x70); }
__device__ __forceinline__ uint32_t f2tf32(float v) {
    uint32_t t;
    asm("cvt.rna.tf32.f32 %0, %1;" : "=r"(t) : "f"(v));
    return t;
}
// scale by s without re-rounding: HMMA's tf32 datapath truncates low bits
__device__ __forceinline__ uint32_t scale_tf32_fast(uint32_t a, float s) {
    return __float_as_uint(__uint_as_float(a) * s);
}
__device__ __forceinline__ void mma_tf32(float d[4], const uint32_t a[4], const uint32_t b[2]) {
    asm volatile(
        "mma.sync.aligned.m16n8k8.row.col.f32.tf32.tf32.f32 "
        "{%0,%1,%2,%3}, {%4,%5,%6,%7}, {%8,%9}, {%0,%1,%2,%3};"
        : "+f"(d[0]), "+f"(d[1]), "+f"(d[2]), "+f"(d[3])
        : "r"(a[0]), "r"(a[1]), "r"(a[2]), "r"(a[3]), "r"(b[0]), "r"(b[1]));
}

// ---------------------------------------------------------------------------
// Gating: logits + gumbel + softmax -> g_weights
// ---------------------------------------------------------------------------
__global__ __launch_bounds__(256) void gating_kernel(
    const float* __restrict__ x, const float* __restrict__ W_att,
    const float* __restrict__ b_att, const float* __restrict__ adaptive_bias,
    const float* __restrict__ gumbel_u)
{
    const int warp = threadIdx.x >> 5, lane = threadIdx.x & 31;
    const int b = blockIdx.x * 8 + warp;
    __shared__ float logits_s[8][EDIM];

    const float* xrow = x + (size_t)b * DDIM;
    float xr[32];
#pragma unroll
    for (int k = 0; k < 32; k++) xr[k] = xrow[k * 32 + lane];

    for (int e = 0; e < EDIM; e++) {
        const float* wrow = W_att + (size_t)e * DDIM;
        float p = 0.f;
#pragma unroll
        for (int k = 0; k < 32; k++) p = fmaf(xr[k], wrow[k * 32 + lane], p);
#pragma unroll
        for (int o = 16; o; o >>= 1) p += __shfl_xor_sync(0xffffffffu, p, o);
        if (lane == 0) logits_s[warp][e] = p;
    }
    __syncwarp();

    float l = logits_s[warp][lane] + b_att[lane] + adaptive_bias[lane];
    float u = gumbel_u[(size_t)b * EDIM + lane];
    float g = -logf(-logf(u + 1e-10f) + 1e-10f);
    float z = l + g;
    float m = z;
#pragma unroll
    for (int o = 16; o; o >>= 1) m = fmaxf(m, __shfl_xor_sync(0xffffffffu, m, o));
    float p = expf(z - m);
    float s = p;
#pragma unroll
    for (int o = 16; o; o >>= 1) s += __shfl_xor_sync(0xffffffffu, s, o);
    g_weights[(size_t)b * EDIM + lane] = p / s;
}

// ---------------------------------------------------------------------------
// Pre-round W_strat to tf32 precision (stored as f32 bits). x needs no
// pre-rounding: the A operand is truncated by HMMA after the FMUL scale.
// ---------------------------------------------------------------------------
__global__ __launch_bounds__(256) void convert_w_tf(const float* __restrict__ W_strat) {
    const size_t i4 = (size_t)blockIdx.x * 256 + threadIdx.x;
    float4 v = ((const float4*)W_strat)[i4];
    uint4 o;
    o.x = f2tf32(v.x); o.y = f2tf32(v.y); o.z = f2tf32(v.z); o.w = f2tf32(v.w);
    ((uint4*)g_Wtf)[i4] = o;
}

// ---------------------------------------------------------------------------
// TF32 mma.sync GEMM, gating weight folded into the A operand.
// ks-outer / e-inner: only one ks of A fragments live (8 regs, was 32) ->
// register headroom for ptxas to hoist LDSMs and hide latency.
// ---------------------------------------------------------------------------
__global__ __launch_bounds__(THREADS, 1) void gemm_tf32(
    const float* __restrict__ x, const float* __restrict__ b_strat)
{
    extern __shared__ char sm[];
    __shared__ float bs_s[EG][BN];
    __shared__ float w_s[EG][BM];

    const int tid = threadIdx.x, wid = tid >> 5, lane = tid & 31;
    const int wm = wid & 3, wn = wid >> 2;          // warp grid 4m x 4n
    const int eg = blockIdx.x & (NGRP - 1);
    const int mt = blockIdx.x >> 3;
    const int row0 = mt * BM;

    {   // stage bias + gating weights (512 elements each)
        (&bs_s[0][0])[tid] = b_strat[(size_t)(eg * EG) * ADIM + tid];
        const int e = tid >> 7, r = tid & 127;
        w_s[e][r] = g_weights[(size_t)(row0 + r) * EDIM + eg * EG + e];
    }

    const uint32_t sbase = smem_u32(sm);

    auto load_stage = [&](int b, int kb) {
        const uint32_t ab = sbase + b * STAGE;
        const char* xs = (const char*)x + ((size_t)row0 * DDIM + kb * BK) * 4;
#pragma unroll
        for (int i = 0; i < 2; i++) {
            const int q = tid + THREADS * i, r = q >> 3, ch = (q & 7) * 16;
            cp_async16(ab + sw128(r * 128 + ch), xs + (size_t)r * DDIM * 4 + ch);
        }
#pragma unroll
        for (int e = 0; e < EG; e++) {
            const uint32_t bb = ab + (1 + e) * TILE_BYTES;
            const char* ws = (const char*)g_Wtf +
                             ((size_t)(eg * EG + e) * ADIM * DDIM + kb * BK) * 4;
#pragma unroll
            for (int i = 0; i < 2; i++) {
                const int q = tid + THREADS * i, r = q >> 3, ch = (q & 7) * 16;
                cp_async16(bb + sw128(r * 128 + ch), ws + (size_t)r * DDIM * 4 + ch);
            }
        }
        cp_commit();
    };

    // hoisted per-thread fragment addressing (sw128 algebra: for byt<128,
    // sw128(row*128+byt) = row*128 + (byt ^ ((row&7)<<4)))
    uint32_t aBase[2], aXor[2];
#pragma unroll
    for (int f = 0; f < 2; f++) {
        const uint32_t row = wm * 32 + f * 16 + (lane & 15);
        aBase[f] = row * 128;
        aXor[f]  = (row & 7) << 4;
    }
    const uint32_t aByt = (lane >> 4) * 16;
    uint32_t bBase[2], bXor[2];
#pragma unroll
    for (int jp = 0; jp < 2; jp++) {
        const uint32_t row = wn * 32 + jp * 16 + ((lane >> 4) & 1) * 8 + (lane & 7);
        bBase[jp] = row * 128;
        bXor[jp]  = (row & 7) << 4;
    }
    const uint32_t bByt = ((lane >> 3) & 1) * 16;

    // per-thread gating weights for own fragment rows
    float wA[EG][2][2];
    __syncthreads();
#pragma unroll
    for (int e = 0; e < EG; e++)
#pragma unroll
        for (int f = 0; f < 2; f++) {
            const int r1 = wm * 32 + f * 16 + (lane >> 2);
            wA[e][f][0] = w_s[e][r1];
            wA[e][f][1] = w_s[e][r1 + 8];
        }

    float accf[2][4][4];
#pragma unroll
    for (int f = 0; f < 2; f++)
#pragma unroll
        for (int j = 0; j < 4; j++)
#pragma unroll
            for (int d = 0; d < 4; d++) accf[f][j][d] = 0.f;

    load_stage(0, 0);

    for (int kb = 0; kb < NKB; kb++) {
        const int buf = kb & 1;
        cp_wait0();
        __syncthreads();

        if (kb + 1 < NKB) load_stage(buf ^ 1, kb + 1);   // overlaps compute

        const uint32_t ab = sbase + buf * STAGE;

#pragma unroll
        for (int ks = 0; ks < 4; ks++) {
            // A fragments for this ks only (8 regs live)
            uint32_t afr[2][4];
#pragma unroll
            for (int f = 0; f < 2; f++) {
                const uint32_t addr = ab + aBase[f] + ((ks * 32 + aByt) ^ aXor[f]);
                asm volatile(
                    "ldmatrix.sync.aligned.m8n8.x4.shared.b16 {%0,%1,%2,%3}, [%4];"
                    : "=r"(afr[f][0]), "=r"(afr[f][1]), "=r"(afr[f][2]), "=r"(afr[f][3])
                    : "r"(addr));
            }
#pragma unroll
            for (int e = 0; e < EG; e++) {
                const uint32_t bb = ab + (1 + e) * TILE_BYTES;
                uint32_t bfr[2][4];
#pragma unroll
                for (int jp = 0; jp < 2; jp++) {
                    const uint32_t addr = bb + bBase[jp] + ((ks * 32 + bByt) ^ bXor[jp]);
                    asm volatile(
                        "ldmatrix.sync.aligned.m8n8.x4.shared.b16 {%0,%1,%2,%3}, [%4];"
                        : "=r"(bfr[jp][0]), "=r"(bfr[jp][1]), "=r"(bfr[jp][2]), "=r"(bfr[jp][3])
                        : "r"(addr));
                }
#pragma unroll
                for (int f = 0; f < 2; f++) {
                    uint32_t sa[4];
                    sa[0] = scale_tf32_fast(afr[f][0], wA[e][f][0]);
                    sa[1] = scale_tf32_fast(afr[f][1], wA[e][f][1]);
                    sa[2] = scale_tf32_fast(afr[f][2], wA[e][f][0]);
                    sa[3] = scale_tf32_fast(afr[f][3], wA[e][f][1]);
#pragma unroll
                    for (int jp = 0; jp < 2; jp++) {
                        mma_tf32(accf[f][2 * jp + 0], sa, &bfr[jp][0]);
                        mma_tf32(accf[f][2 * jp + 1], sa, &bfr[jp][2]);
                    }
                }
            }
        }
    }

    // add bias term: accf += sum_e w[row,e] * bias[e,col]
#pragma unroll
    for (int e = 0; e < EG; e++) {
#pragma unroll
        for (int f = 0; f < 2; f++) {
            const float w1 = wA[e][f][0], w2 = wA[e][f][1];
#pragma unroll
            for (int j = 0; j < 4; j++) {
                const int c0 = wn * 32 + j * 8 + (lane & 3) * 2;
                const float b0 = bs_s[e][c0], b1 = bs_s[e][c0 + 1];
                accf[f][j][0] = fmaf(w1, b0, accf[f][j][0]);
                accf[f][j][1] = fmaf(w1, b1, accf[f][j][1]);
                accf[f][j][2] = fmaf(w2, b0, accf[f][j][2]);
                accf[f][j][3] = fmaf(w2, b1, accf[f][j][3]);
            }
        }
    }

    // write to per-group scratch
#pragma unroll
    for (int f = 0; f < 2; f++) {
        const int r1 = row0 + wm * 32 + f * 16 + (lane >> 2);
#pragma unroll
        for (int j = 0; j < 4; j++) {
            const int c0 = wn * 32 + j * 8 + (lane & 3) * 2;
            float* base = g_scratch + (size_t)eg * BDIM * ADIM;
            *(float2*)&base[(size_t)r1 * ADIM + c0] =
                make_float2(accf[f][j][0], accf[f][j][1]);
            *(float2*)&base[(size_t)(r1 + 8) * ADIM + c0] =
                make_float2(accf[f][j][2], accf[f][j][3]);
        }
    }
}

// ---------------------------------------------------------------------------
// Final reduce: out = sum over 8 expert-group partials
// ---------------------------------------------------------------------------
__global__ __launch_bounds__(256) void reduce_kernel(float* __restrict__ out) {
    const size_t idx = (size_t)blockIdx.x * 256 + threadIdx.x;
    const float4* s = (const float4*)g_scratch;
    float4 a = s[idx];
#pragma unroll
    for (int g = 1; g < NGRP; g++) {
        float4 t = s[(size_t)g * (BDIM * ADIM / 4) + idx];
        a.x += t.x; a.y += t.y; a.z += t.z; a.w += t.w;
    }
    ((float4*)out)[idx] = a;
}

// ---------------------------------------------------------------------------
extern "C" void kernel_launch(void* const* d_in, const int* in_sizes, int n_in,
                              void* d_out, int out_size) {
    const float* x             = (const float*)d_in[0];
    const float* W_att         = (const float*)d_in[1];
    const float* b_att         = (const float*)d_in[2];
    const float* adaptive_bias = (const float*)d_in[3];
    const float* W_strat       = (const float*)d_in[4];
    const float* b_strat       = (const float*)d_in[5];
    const float* gumbel_u      = (const float*)d_in[6];
    float* out = (float*)d_out;

    cudaFuncSetAttribute(gemm_tf32, cudaFuncAttributeMaxDynamicSharedMemorySize, SMEM_DYN);

    gating_kernel<<<BDIM / 8, 256>>>(x, W_att, b_att, adaptive_bias, gumbel_u);
    convert_w_tf<<<(EDIM * ADIM * DDIM / 4) / 256, 256>>>(W_strat);
    gemm_tf32<<<(BDIM / BM) * NGRP, THREADS, SMEM_DYN>>>(x, b_strat);
    reduce_kernel<<<(BDIM * ADIM / 4) / 256, 256>>>(out);
}

// round 13
// speedup vs baseline: 1.1627x; 1.0106x over previous
#include <cuda_runtime.h>
#include <cstdint>

#define BDIM 8192
#define DDIM 1024
#define EDIM 32
#define ADIM 128
#define EG   4
#define NGRP (EDIM / EG)     // 8
#define BM   64
#define BN   128
#define BK   32              // 32 fp32 = 128 B per smem row
#define NKB  (DDIM / BK)     // 32
#define THREADS 256
#define A_TILE_BYTES (BM * BK * 4)           // 8192
#define B_TILE_BYTES (BN * BK * 4)           // 16384
#define STAGE      (A_TILE_BYTES + EG * B_TILE_BYTES)   // 73728
#define SMEM_DYN   (2 * STAGE)               // 147456 double buffered

// ---------------- device scratch ----------------
__device__ __align__(1024) float g_Wtf[(size_t)EDIM * ADIM * DDIM];
__device__ float g_weights[BDIM * EDIM];
__device__ float g_scratch[(size_t)NGRP * BDIM * ADIM];

// ---------------- helpers ----------------
__device__ __forceinline__ uint32_t smem_u32(const void* p) {
    uint32_t a;
    asm("{ .reg .u64 t; cvta.to.shared.u64 t, %1; cvt.u32.u64 %0, t; }" : "=r"(a) : "l"(p));
    return a;
}
__device__ __forceinline__ void cp_async16(uint32_t dst, const void* src) {
    asm volatile("cp.async.cg.shared.global [%0], [%1], 16;" :: "r"(dst), "l"(src));
}
__device__ __forceinline__ void cp_commit() { asm volatile("cp.async.commit_group;"); }
__device__ __forceinline__ void cp_wait0()  { asm volatile("cp.async.wait_group 0;" ::: "memory"); }
__device__ __forceinline__ uint32_t sw128(uint32_t o) { return o ^ ((o >> 3) & 0x70); }
__device__ __forceinline__ uint32_t f2tf32(float v) {
    uint32_t t;
    asm("cvt.rna.tf32.f32 %0, %1;" : "=r"(t) : "f"(v));
    return t;
}
// scale by s without re-rounding: HMMA's tf32 datapath truncates low bits
__device__ __forceinline__ uint32_t scale_tf32_fast(uint32_t a, float s) {
    return __float_as_uint(__uint_as_float(a) * s);
}
__device__ __forceinline__ void mma_tf32(float d[4], const uint32_t a[4], const uint32_t b[2]) {
    asm volatile(
        "mma.sync.aligned.m16n8k8.row.col.f32.tf32.tf32.f32 "
        "{%0,%1,%2,%3}, {%4,%5,%6,%7}, {%8,%9}, {%0,%1,%2,%3};"
        : "+f"(d[0]), "+f"(d[1]), "+f"(d[2]), "+f"(d[3])
        : "r"(a[0]), "r"(a[1]), "r"(a[2]), "r"(a[3]), "r"(b[0]), "r"(b[1]));
}

// ---------------------------------------------------------------------------
// Gating: logits + gumbel + softmax -> g_weights
// ---------------------------------------------------------------------------
__global__ __launch_bounds__(256) void gating_kernel(
    const float* __restrict__ x, const float* __restrict__ W_att,
    const float* __restrict__ b_att, const float* __restrict__ adaptive_bias,
    const float* __restrict__ gumbel_u)
{
    const int warp = threadIdx.x >> 5, lane = threadIdx.x & 31;
    const int b = blockIdx.x * 8 + warp;
    __shared__ float logits_s[8][EDIM];

    const float* xrow = x + (size_t)b * DDIM;
    float xr[32];
#pragma unroll
    for (int k = 0; k < 32; k++) xr[k] = xrow[k * 32 + lane];

    for (int e = 0; e < EDIM; e++) {
        const float* wrow = W_att + (size_t)e * DDIM;
        float p = 0.f;
#pragma unroll
        for (int k = 0; k < 32; k++) p = fmaf(xr[k], wrow[k * 32 + lane], p);
#pragma unroll
        for (int o = 16; o; o >>= 1) p += __shfl_xor_sync(0xffffffffu, p, o);
        if (lane == 0) logits_s[warp][e] = p;
    }
    __syncwarp();

    float l = logits_s[warp][lane] + b_att[lane] + adaptive_bias[lane];
    float u = gumbel_u[(size_t)b * EDIM + lane];
    float g = -logf(-logf(u + 1e-10f) + 1e-10f);
    float z = l + g;
    float m = z;
#pragma unroll
    for (int o = 16; o; o >>= 1) m = fmaxf(m, __shfl_xor_sync(0xffffffffu, m, o));
    float p = expf(z - m);
    float s = p;
#pragma unroll
    for (int o = 16; o; o >>= 1) s += __shfl_xor_sync(0xffffffffu, s, o);
    g_weights[(size_t)b * EDIM + lane] = p / s;
}

// ---------------------------------------------------------------------------
// Pre-round W_strat to tf32 precision (stored as f32 bits)
// ---------------------------------------------------------------------------
__global__ __launch_bounds__(256) void convert_w_tf(const float* __restrict__ W_strat) {
    const size_t i4 = (size_t)blockIdx.x * 256 + threadIdx.x;
    float4 v = ((const float4*)W_strat)[i4];
    uint4 o;
    o.x = f2tf32(v.x); o.y = f2tf32(v.y); o.z = f2tf32(v.z); o.w = f2tf32(v.w);
    ((uint4*)g_Wtf)[i4] = o;
}

// ---------------------------------------------------------------------------
// TF32 mma.sync GEMM, gating weight folded into the A operand.
// BM=64, grid=1024: wave-quantization makespan 7/6.92 = 1.012 (was 4/3.46
// = 1.156 at BM=128). 8 warps (2m x 4n), warp tile 32x32 -- inner loop
// identical to the proven R12 datapath.
// ---------------------------------------------------------------------------
__global__ __launch_bounds__(THREADS, 1) void gemm_tf32(
    const float* __restrict__ x, const float* __restrict__ b_strat)
{
    extern __shared__ char sm[];
    __shared__ float bs_s[EG][BN];
    __shared__ float w_s[EG][BM];

    const int tid = threadIdx.x, wid = tid >> 5, lane = tid & 31;
    const int wm = wid & 1, wn = wid >> 1;          // warp grid 2m x 4n
    const int eg = blockIdx.x & (NGRP - 1);
    const int mt = blockIdx.x >> 3;
    const int row0 = mt * BM;

    {   // stage bias (EG*BN=512) + gating weights (EG*BM=256)
#pragma unroll
        for (int i = 0; i < 2; i++)
            (&bs_s[0][0])[tid + 256 * i] = b_strat[(size_t)(eg * EG) * ADIM + tid + 256 * i];
        const int e = tid >> 6, r = tid & 63;
        w_s[e][r] = g_weights[(size_t)(row0 + r) * EDIM + eg * EG + e];
    }

    const uint32_t sbase = smem_u32(sm);

    auto load_stage = [&](int b, int kb) {
        const uint32_t ab = sbase + b * STAGE;
        const char* xs = (const char*)x + ((size_t)row0 * DDIM + kb * BK) * 4;
#pragma unroll
        for (int i = 0; i < 2; i++) {                // A: 512 chunks
            const int q = tid + THREADS * i, r = q >> 3, ch = (q & 7) * 16;
            cp_async16(ab + sw128(r * 128 + ch), xs + (size_t)r * DDIM * 4 + ch);
        }
#pragma unroll
        for (int e = 0; e < EG; e++) {               // B: 4 x 1024 chunks
            const uint32_t bb = ab + A_TILE_BYTES + e * B_TILE_BYTES;
            const char* ws = (const char*)g_Wtf +
                             ((size_t)(eg * EG + e) * ADIM * DDIM + kb * BK) * 4;
#pragma unroll
            for (int i = 0; i < 4; i++) {
                const int q = tid + THREADS * i, r = q >> 3, ch = (q & 7) * 16;
                cp_async16(bb + sw128(r * 128 + ch), ws + (size_t)r * DDIM * 4 + ch);
            }
        }
        cp_commit();
    };

    // hoisted fragment addressing (sw128(row*128+byt) = row*128 + (byt ^ ((row&7)<<4)))
    uint32_t aBase[2], aXor[2];
#pragma unroll
    for (int f = 0; f < 2; f++) {
        const uint32_t row = wm * 32 + f * 16 + (lane & 15);
        aBase[f] = row * 128;
        aXor[f]  = (row & 7) << 4;
    }
    const uint32_t aByt = (lane >> 4) * 16;
    uint32_t bBase[2], bXor[2];
#pragma unroll
    for (int jp = 0; jp < 2; jp++) {
        const uint32_t row = wn * 32 + jp * 16 + ((lane >> 4) & 1) * 8 + (lane & 7);
        bBase[jp] = row * 128;
        bXor[jp]  = (row & 7) << 4;
    }
    const uint32_t bByt = ((lane >> 3) & 1) * 16;

    // per-thread gating weights for own fragment rows
    float wA[EG][2][2];
    __syncthreads();
#pragma unroll
    for (int e = 0; e < EG; e++)
#pragma unroll
        for (int f = 0; f < 2; f++) {
            const int r1 = wm * 32 + f * 16 + (lane >> 2);
            wA[e][f][0] = w_s[e][r1];
            wA[e][f][1] = w_s[e][r1 + 8];
        }

    float accf[2][4][4];
#pragma unroll
    for (int f = 0; f < 2; f++)
#pragma unroll
        for (int j = 0; j < 4; j++)
#pragma unroll
            for (int d = 0; d < 4; d++) accf[f][j][d] = 0.f;

    load_stage(0, 0);

    for (int kb = 0; kb < NKB; kb++) {
        const int buf = kb & 1;
        cp_wait0();
        __syncthreads();

        if (kb + 1 < NKB) load_stage(buf ^ 1, kb + 1);   // overlaps compute

        const uint32_t ab = sbase + buf * STAGE;

#pragma unroll
        for (int ks = 0; ks < 4; ks++) {
            uint32_t afr[2][4];
#pragma unroll
            for (int f = 0; f < 2; f++) {
                const uint32_t addr = ab + aBase[f] + ((ks * 32 + aByt) ^ aXor[f]);
                asm volatile(
                    "ldmatrix.sync.aligned.m8n8.x4.shared.b16 {%0,%1,%2,%3}, [%4];"
                    : "=r"(afr[f][0]), "=r"(afr[f][1]), "=r"(afr[f][2]), "=r"(afr[f][3])
                    : "r"(addr));
            }
#pragma unroll
            for (int e = 0; e < EG; e++) {
                const uint32_t bb = ab + A_TILE_BYTES + e * B_TILE_BYTES;
                uint32_t bfr[2][4];
#pragma unroll
                for (int jp = 0; jp < 2; jp++) {
                    const uint32_t addr = bb + bBase[jp] + ((ks * 32 + bByt) ^ bXor[jp]);
                    asm volatile(
                        "ldmatrix.sync.aligned.m8n8.x4.shared.b16 {%0,%1,%2,%3}, [%4];"
                        : "=r"(bfr[jp][0]), "=r"(bfr[jp][1]), "=r"(bfr[jp][2]), "=r"(bfr[jp][3])
                        : "r"(addr));
                }
#pragma unroll
                for (int f = 0; f < 2; f++) {
                    uint32_t sa[4];
                    sa[0] = scale_tf32_fast(afr[f][0], wA[e][f][0]);
                    sa[1] = scale_tf32_fast(afr[f][1], wA[e][f][1]);
                    sa[2] = scale_tf32_fast(afr[f][2], wA[e][f][0]);
                    sa[3] = scale_tf32_fast(afr[f][3], wA[e][f][1]);
#pragma unroll
                    for (int jp = 0; jp < 2; jp++) {
                        mma_tf32(accf[f][2 * jp + 0], sa, &bfr[jp][0]);
                        mma_tf32(accf[f][2 * jp + 1], sa, &bfr[jp][2]);
                    }
                }
            }
        }
    }

    // add bias term: accf += sum_e w[row,e] * bias[e,col]
#pragma unroll
    for (int e = 0; e < EG; e++) {
#pragma unroll
        for (int f = 0; f < 2; f++) {
            const float w1 = wA[e][f][0], w2 = wA[e][f][1];
#pragma unroll
            for (int j = 0; j < 4; j++) {
                const int c0 = wn * 32 + j * 8 + (lane & 3) * 2;
                const float b0 = bs_s[e][c0], b1 = bs_s[e][c0 + 1];
                accf[f][j][0] = fmaf(w1, b0, accf[f][j][0]);
                accf[f][j][1] = fmaf(w1, b1, accf[f][j][1]);
                accf[f][j][2] = fmaf(w2, b0, accf[f][j][2]);
                accf[f][j][3] = fmaf(w2, b1, accf[f][j][3]);
            }
        }
    }

    // write to per-group scratch
#pragma unroll
    for (int f = 0; f < 2; f++) {
        const int r1 = row0 + wm * 32 + f * 16 + (lane >> 2);
#pragma unroll
        for (int j = 0; j < 4; j++) {
            const int c0 = wn * 32 + j * 8 + (lane & 3) * 2;
            float* base = g_scratch + (size_t)eg * BDIM * ADIM;
            *(float2*)&base[(size_t)r1 * ADIM + c0] =
                make_float2(accf[f][j][0], accf[f][j][1]);
            *(float2*)&base[(size_t)(r1 + 8) * ADIM + c0] =
                make_float2(accf[f][j][2], accf[f][j][3]);
        }
    }
}

// ---------------------------------------------------------------------------
// Final reduce: out = sum over 8 expert-group partials
// ---------------------------------------------------------------------------
__global__ __launch_bounds__(256) void reduce_kernel(float* __restrict__ out) {
    const size_t idx = (size_t)blockIdx.x * 256 + threadIdx.x;
    const float4* s = (const float4*)g_scratch;
    float4 a = s[idx];
#pragma unroll
    for (int g = 1; g < NGRP; g++) {
        float4 t = s[(size_t)g * (BDIM * ADIM / 4) + idx];
        a.x += t.x; a.y += t.y; a.z += t.z; a.w += t.w;
    }
    ((float4*)out)[idx] = a;
}

// ---------------------------------------------------------------------------
extern "C" void kernel_launch(void* const* d_in, const int* in_sizes, int n_in,
                              void* d_out, int out_size) {
    const float* x             = (const float*)d_in[0];
    const float* W_att         = (const float*)d_in[1];
    const float* b_att         = (const float*)d_in[2];
    const float* adaptive_bias = (const float*)d_in[3];
    const float* W_strat       = (const float*)d_in[4];
    const float* b_strat       = (const float*)d_in[5];
    const float* gumbel_u      = (const float*)d_in[6];
    float* out = (float*)d_out;

    cudaFuncSetAttribute(gemm_tf32, cudaFuncAttributeMaxDynamicSharedMemorySize, SMEM_DYN);

    gating_kernel<<<BDIM / 8, 256>>>(x, W_att, b_att, adaptive_bias, gumbel_u);
    convert_w_tf<<<(EDIM * ADIM * DDIM / 4) / 256, 256>>>(W_strat);
    gemm_tf32<<<(BDIM / BM) * NGRP, THREADS, SMEM_DYN>>>(x, b_strat);
    reduce_kernel<<<(BDIM * ADIM / 4) / 256, 256>>>(out);
}